// round 3
// baseline (speedup 1.0000x reference)
#include <cuda_runtime.h>
#include <cstdint>

#define T_LEN 2048
#define B_SZ  256
#define IN_DIM 182
#define H_DIM  64
#define G3     192   // 3*H

typedef unsigned long long ull;

// ~403 MB scratch for the input-projection output IG[B*T, 192]
__device__ float g_ig[(size_t)B_SZ * T_LEN * G3];

// ---- packed f32x2 helpers (Blackwell FFMA2 path, full fp32 precision) ----
__device__ __forceinline__ void ffma2(ull& acc, ull a, ull b) {
    asm("fma.rn.f32x2 %0, %1, %2, %0;" : "+l"(acc) : "l"(a), "l"(b));
}
__device__ __forceinline__ ull fadd2(ull a, ull b) {
    ull d; asm("add.rn.f32x2 %0, %1, %2;" : "=l"(d) : "l"(a), "l"(b)); return d;
}
__device__ __forceinline__ void unpack2(float& lo, float& hi, ull v) {
    asm("mov.b64 {%0, %1}, %2;" : "=f"(lo), "=f"(hi) : "l"(v));
}

// ---------------------------------------------------------------------------
// Kernel A: IG = X(BT x 182) @ W_ih^T(182 x 192) + bias
// BM=64, BN=192, BK=16, 256 threads, per-thread tile 4x12 (as 4x6 f32x2 pairs).
// A smem tile stored DUPLICATED so splat pairs come straight from LDS.128.
// ---------------------------------------------------------------------------
__global__ __launch_bounds__(256) void ig_gemm(const float* __restrict__ X,
                                               const float* __restrict__ Wih,
                                               const float* __restrict__ bias)
{
    __shared__ float As2[16][132];   // [k][2m] duplicated: (a,a) pairs
    __shared__ float Bs[16][196];    // [k][n]

    const int tid = threadIdx.x;
    const int mBase = blockIdx.x * 64;
    const int mg = tid >> 4;   // 0..15 : compute row group (4 rows)
    const int ng = tid & 15;   // 0..15 : compute col group (12 cols = 6 pairs)
    const int lm = tid >> 4;   // loader group
    const int lk = tid & 15;   // loader k within tile

    ull acc2[4][6];
#pragma unroll
    for (int i = 0; i < 4; i++)
#pragma unroll
        for (int j = 0; j < 6; j++) acc2[i][j] = 0ull;

    const int NT = (IN_DIM + 15) / 16;   // 12 k-tiles

    float aReg[4], bReg[12];
#pragma unroll
    for (int i = 0; i < 4; i++) {
        int k = lk;
        aReg[i] = (k < IN_DIM) ? X[(size_t)(mBase + lm + i * 16) * IN_DIM + k] : 0.f;
    }
#pragma unroll
    for (int i = 0; i < 12; i++) {
        int k = lk;
        bReg[i] = (k < IN_DIM) ? Wih[(size_t)(lm + i * 16) * IN_DIM + k] : 0.f;
    }

    for (int t = 0; t < NT; t++) {
#pragma unroll
        for (int i = 0; i < 4; i++) {
            int m2 = (lm + i * 16) * 2;
            As2[lk][m2] = aReg[i];
            As2[lk][m2 + 1] = aReg[i];
        }
#pragma unroll
        for (int i = 0; i < 12; i++) Bs[lk][lm + i * 16] = bReg[i];
        __syncthreads();

        if (t + 1 < NT) {
            const int k0n = (t + 1) * 16;
#pragma unroll
            for (int i = 0; i < 4; i++) {
                int k = k0n + lk;
                aReg[i] = (k < IN_DIM) ? X[(size_t)(mBase + lm + i * 16) * IN_DIM + k] : 0.f;
            }
#pragma unroll
            for (int i = 0; i < 12; i++) {
                int k = k0n + lk;
                bReg[i] = (k < IN_DIM) ? Wih[(size_t)(lm + i * 16) * IN_DIM + k] : 0.f;
            }
        }

#pragma unroll
        for (int k = 0; k < 16; k++) {
            // splat pairs (a0,a0),(a1,a1),(a2,a2),(a3,a3) via two LDS.128
            ulonglong2 aP0 = *(const ulonglong2*)&As2[k][mg * 8];
            ulonglong2 aP1 = *(const ulonglong2*)&As2[k][mg * 8 + 4];
            // b pairs (b0,b1)..(b10,b11) via three LDS.128
            ulonglong2 bP0 = *(const ulonglong2*)&Bs[k][ng * 12];
            ulonglong2 bP1 = *(const ulonglong2*)&Bs[k][ng * 12 + 4];
            ulonglong2 bP2 = *(const ulonglong2*)&Bs[k][ng * 12 + 8];
            ull aP[4] = {aP0.x, aP0.y, aP1.x, aP1.y};
            ull bP[6] = {bP0.x, bP0.y, bP1.x, bP1.y, bP2.x, bP2.y};
#pragma unroll
            for (int i = 0; i < 4; i++)
#pragma unroll
                for (int j = 0; j < 6; j++)
                    ffma2(acc2[i][j], aP[i], bP[j]);
        }
        __syncthreads();
    }

    // epilogue: add bias (packed), store pairs
    ull bp[6];
#pragma unroll
    for (int j = 0; j < 6; j++) bp[j] = *(const ull*)&bias[ng * 12 + 2 * j];
#pragma unroll
    for (int i = 0; i < 4; i++) {
        size_t row = (size_t)(mBase + mg * 4 + i);
        ull* o = (ull*)&g_ig[row * G3 + ng * 12];
#pragma unroll
        for (int j = 0; j < 6; j++) o[j] = fadd2(acc2[i][j], bp[j]);
    }
}

// ---------------------------------------------------------------------------
// Kernel B: GRU scan. One CTA per batch element, 192 threads.
// Thread j owns gate-row j of W_hh as 32 packed f32x2 pairs.
// ---------------------------------------------------------------------------
__device__ __forceinline__ float fsigmoid(float x) {
    return __fdividef(1.f, 1.f + __expf(-x));
}
__device__ __forceinline__ float ftanh(float x) {
    return __fdividef(2.f, 1.f + __expf(-2.f * x)) - 1.f;
}

__global__ __launch_bounds__(192) void gru_scan(const float* __restrict__ whh,      // [192,64]
                                                const float* __restrict__ bias_n,   // [64]
                                                const float* __restrict__ wout,     // [2,64]
                                                const float* __restrict__ out_bias, // [2]
                                                float* __restrict__ out)            // [B,2]
{
    const int b = blockIdx.x;
    const int j = threadIdx.x;           // 0..191

    __shared__ float sh_h[64];
    __shared__ float sh_pre[192];        // j<128: ig+hg ; j>=128: ig_n
    __shared__ float sh_b[64];           // hg_n + bias_n

    // W_hh row j as 32 packed pairs (64 regs)
    ull wp[32];
#pragma unroll
    for (int q = 0; q < 32; q++) wp[q] = *(const ull*)&whh[j * 64 + 2 * q];

    const float bn = (j >= 128) ? bias_n[j - 128] : 0.f;

    if (j < 64) sh_h[j] = 0.f;

    const float* igp = g_ig + (size_t)b * T_LEN * G3 + j;
    float ig_next = igp[0];
    __syncthreads();

    for (int t = 0; t < T_LEN; t++) {
        const float igc = ig_next;
        if (t < T_LEN - 1) ig_next = igp[(size_t)(t + 1) * G3];

        // hg_j = dot(W_hh[j,:], h) with packed pairs, 4 independent chains
        ull a0 = 0ull, a1 = 0ull, a2 = 0ull, a3 = 0ull;
#pragma unroll
        for (int q = 0; q < 32; q += 4) {
            ulonglong2 h01 = *(const ulonglong2*)&sh_h[2 * q];      // pairs q, q+1
            ulonglong2 h23 = *(const ulonglong2*)&sh_h[2 * q + 4];  // pairs q+2, q+3
            ffma2(a0, wp[q],     h01.x);
            ffma2(a1, wp[q + 1], h01.y);
            ffma2(a2, wp[q + 2], h23.x);
            ffma2(a3, wp[q + 3], h23.y);
        }
        float s0, s1, s2, s3, s4, s5, s6, s7;
        unpack2(s0, s1, a0); unpack2(s2, s3, a1);
        unpack2(s4, s5, a2); unpack2(s6, s7, a3);
        const float hg = ((s0 + s1) + (s2 + s3)) + ((s4 + s5) + (s6 + s7));

        if (j < 128) {
            sh_pre[j] = igc + hg;
        } else {
            sh_pre[j] = igc;
            sh_b[j - 128] = hg + bn;
        }
        __syncthreads();

        if (j < 64) {
            const float r = fsigmoid(sh_pre[j]);
            const float z = fsigmoid(sh_pre[64 + j]);
            const float n = ftanh(sh_pre[128 + j] + r * sh_b[j]);
            const float h = sh_h[j];
            sh_h[j] = n + z * (h - n);
        }
        __syncthreads();
    }

    // readout: OUT=2
    if (j < 2) {
        float acc = 0.f;
#pragma unroll 8
        for (int k = 0; k < 64; k++) acc += wout[j * 64 + k] * sh_h[k];
        out[b * 2 + j] = fsigmoid(acc + out_bias[j]);
    }
}

// ---------------------------------------------------------------------------
extern "C" void kernel_launch(void* const* d_in, const int* in_sizes, int n_in,
                              void* d_out, int out_size)
{
    const float* x        = (const float*)d_in[0];   // (256,2048,182)
    const float* wih      = (const float*)d_in[1];   // (192,182)
    const float* whh      = (const float*)d_in[2];   // (192,64)
    const float* bias     = (const float*)d_in[3];   // (192,)
    const float* bias_n   = (const float*)d_in[4];   // (64,)
    const float* wout     = (const float*)d_in[5];   // (2,64)
    const float* out_bias = (const float*)d_in[6];   // (2,)
    float* out = (float*)d_out;                      // (256,2)

    const int BT = B_SZ * T_LEN;
    ig_gemm<<<BT / 64, 256>>>(x, wih, bias);
    gru_scan<<<B_SZ, 192>>>(whh, bias_n, wout, out_bias, out);
}